// round 9
// baseline (speedup 1.0000x reference)
#include <cuda_runtime.h>
#include <math.h>

// ---------------- problem constants ----------------
#define KS    11
#define HI    384
#define HO    512
#define HOUT  (HO - KS + 1)     // 502
#define TILE  32
#define PATCH (TILE + KS - 1)   // 42
#define SW    43                // s12 row stride (ull), odd -> conflict-free row walks
#define HS    33                // hbuf row stride
#define NT    ((HOUT + TILE - 1) / TILE)  // 16
#define HTASKS (PATCH * 8)      // 336

typedef unsigned long long ull;

// Gaussian weights (sigma=1.5, ks=11), double-normalized, rounded to f32.
#define GW0  0.0010283801f
#define GW1  0.0075987582f
#define GW2  0.0360007722f
#define GW3  0.1093606884f
#define GW4  0.2130055383f
#define GW5  0.2660117256f

__device__ double        g_accum = 0.0;
__device__ unsigned int  g_count = 0;

// ---------------- f32x2 packed helpers ----------------
__device__ __forceinline__ ull splat2(float g) {
    ull r; asm("mov.b64 %0, {%1, %1};" : "=l"(r) : "f"(g)); return r;
}
__device__ __forceinline__ void up2(ull v, float& lo, float& hi) {
    asm("mov.b64 {%0, %1}, %2;" : "=f"(lo), "=f"(hi) : "l"(v));
}
__device__ __forceinline__ ull pk2(float lo, float hi) {
    ull r; asm("mov.b64 %0, {%1, %2};" : "=l"(r) : "f"(lo), "f"(hi)); return r;
}
__device__ __forceinline__ ull pfma(ull a, ull b, ull c) {
    ull d; asm("fma.rn.f32x2 %0, %1, %2, %3;" : "=l"(d) : "l"(a), "l"(b), "l"(c)); return d;
}
__device__ __forceinline__ ull pmul(ull a, ull b) {
    ull d; asm("mul.rn.f32x2 %0, %1, %2;" : "=l"(d) : "l"(a), "l"(b)); return d;
}

#define GWC(k) ((k) < 6 ? (k) : 10 - (k))

// ---------------- single fused kernel ----------------
__global__ void __launch_bounds__(256, 4)
ssim_tile_kernel(const float* __restrict__ input,   // [96, 384, 384]
                 const float* __restrict__ target,  // [96, 512, 512]
                 float* __restrict__ out,
                 long long count, unsigned int nblocks)
{
    __shared__ ull   s12[PATCH][SW];      // (img1, img2) interleaved   14448 B
    __shared__ ull   hmu[PATCH][HS];      //                            11088 B
    __shared__ ull   hsq[PATCH][HS];      //                            11088 B
    __shared__ float hx12[PATCH][HS];     //                             5544 B
    __shared__ int   riy0[PATCH], riy1[PATCH], rgy[PATCH];
    __shared__ float rwy[PATCH];
    __shared__ int   cix0[PATCH], cix1[PATCH], cgx[PATCH];
    __shared__ float cwx[PATCH];
    __shared__ float redbuf[8];

    const int img = blockIdx.z;
    const int ty0 = blockIdx.y * TILE;
    const int tx0 = blockIdx.x * TILE;
    const int tid = threadIdx.x;

    const float GW[6] = {GW0, GW1, GW2, GW3, GW4, GW5};
    ull CS[6];
    #pragma unroll
    for (int k = 0; k < 6; k++) CS[k] = splat2(GW[k]);

    const float* inp = input  + (size_t)img * (HI * HI);
    const float* tgt = target + (size_t)img * (HO * HO);

    // ---- build bilinear tables (rows: tid<42, cols: tid in [128,170)) ----
    if (tid < PATCH) {
        int gy = min(ty0 + tid, HO - 1);
        int py = gy * (HI - 1);
        int iy0 = py / (HO - 1);
        riy0[tid] = iy0 * HI;
        riy1[tid] = min(iy0 + 1, HI - 1) * HI;
        rwy[tid]  = (float)(py - iy0 * (HO - 1)) * (1.0f / (float)(HO - 1));
        rgy[tid]  = gy * HO;
    }
    if (tid >= 128 && tid < 128 + PATCH) {
        int c = tid - 128;
        int gx = min(tx0 + c, HO - 1);
        int px = gx * (HI - 1);
        int ix0 = px / (HO - 1);
        cix0[c] = ix0;
        cix1[c] = min(ix0 + 1, HI - 1);
        cwx[c]  = (float)(px - ix0 * (HO - 1)) * (1.0f / (float)(HO - 1));
        cgx[c]  = gx;
    }
    __syncthreads();

    // ---- load: target direct, img1 bilinear via tables ----
    for (int e = tid; e < PATCH * PATCH; e += 256) {
        int r = e / PATCH;
        int c = e - r * PATCH;

        float t2 = tgt[rgy[r] + cgx[c]];

        int   y0 = riy0[r], y1 = riy1[r];
        float wy = rwy[r];
        int   x0 = cix0[c], x1 = cix1[c];
        float wx = cwx[c];

        float a  = inp[y0 + x0];
        float b  = inp[y0 + x1];
        float cc = inp[y1 + x0];
        float d  = inp[y1 + x1];
        float top = a  + (b - a)  * wx;
        float bot = cc + (d - cc) * wx;
        float v1  = top + (bot - top) * wy;

        s12[r][c] = pk2(v1, t2);
    }
    __syncthreads();

    // ---- horizontal pass: 4 output cols per task, sliding 14-tap window.
    //      Conflict-free map: consecutive lanes walk consecutive rows. ----
    for (int e = tid; e < HTASKS; e += 256) {
        int g  = e / PATCH;         // column group 0..7
        int r  = e - g * PATCH;     // row 0..41
        int c0 = g << 2;

        ull aM[4] = {0, 0, 0, 0};
        ull aS[4] = {0, 0, 0, 0};
        float aX[4] = {0.f, 0.f, 0.f, 0.f};

        #pragma unroll
        for (int j = 0; j < 14; j++) {
            ull pk = s12[r][c0 + j];
            float p1, p2;
            up2(pk, p1, p2);
            ull sq = pmul(pk, pk);
            float p12 = p1 * p2;
            #pragma unroll
            for (int o = 0; o < 4; o++) {
                int k = j - o;
                if (k >= 0 && k < KS) {
                    aM[o] = pfma(pk, CS[GWC(k)], aM[o]);
                    aS[o] = pfma(sq, CS[GWC(k)], aS[o]);
                    aX[o] = fmaf(GW[GWC(k)], p12, aX[o]);
                }
            }
        }
        #pragma unroll
        for (int o = 0; o < 4; o++) {
            hmu[r][c0 + o]  = aM[o];
            hsq[r][c0 + o]  = aS[o];
            hx12[r][c0 + o] = aX[o];
        }
    }
    __syncthreads();

    // ---- vertical pass: 8 warps x 4 rows/thread, sliding 14-tap window ----
    const int lx = tid & 31;
    const int o0 = (tid >> 5) << 2;     // warp w -> rows 4w..4w+3

    ull aM[4], aS[4];
    float aX[4];
    #pragma unroll
    for (int o = 0; o < 4; o++) { aM[o] = 0; aS[o] = 0; aX[o] = 0.f; }

    #pragma unroll
    for (int rel = 0; rel < 14; rel++) {
        int rr = o0 + rel;
        ull vM   = hmu[rr][lx];
        ull vS   = hsq[rr][lx];
        float vX = hx12[rr][lx];
        #pragma unroll
        for (int o = 0; o < 4; o++) {
            int k = rel - o;
            if (k >= 0 && k < KS) {
                aM[o] = pfma(vM, CS[GWC(k)], aM[o]);
                aS[o] = pfma(vS, CS[GWC(k)], aS[o]);
                aX[o] = fmaf(GW[GWC(k)], vX, aX[o]);
            }
        }
    }

    // ---- SSIM map + local sum ----
    const float C1 = 1e-4f;
    const float C2 = 9e-4f;
    float lsum = 0.f;
    const int gx = tx0 + lx;

    #pragma unroll
    for (int o = 0; o < 4; o++) {
        int gy = ty0 + o0 + o;
        if (gy < HOUT && gx < HOUT) {
            float mu1, mu2, x11, x22;
            up2(aM[o], mu1, mu2);
            up2(aS[o], x11, x22);
            float mu1sq = mu1 * mu1;
            float mu2sq = mu2 * mu2;
            float mu12  = mu1 * mu2;
            float sig1  = x11 - mu1sq;
            float sig2  = x22 - mu2sq;
            float sig12 = aX[o] - mu12;
            float v1 = 2.0f * sig12 + C2;
            float v2 = sig1 + sig2 + C2;
            float num = (2.0f * mu12 + C1) * v1;
            float den = (mu1sq + mu2sq + C1) * v2;
            lsum += __fdividef(num, den);
        }
    }

    // ---- block reduction (8 warps) ----
    #pragma unroll
    for (int off = 16; off > 0; off >>= 1)
        lsum += __shfl_down_sync(0xFFFFFFFFu, lsum, off);
    int lane = tid & 31;
    int wid  = tid >> 5;
    if (lane == 0) redbuf[wid] = lsum;
    __syncthreads();
    if (tid == 0) {
        float v = 0.f;
        #pragma unroll
        for (int w = 0; w < 8; w++) v += redbuf[w];
        atomicAdd(&g_accum, (double)v);
        __threadfence();
        unsigned int old = atomicAdd(&g_count, 1u);
        if (old == nblocks - 1u) {
            double mean = g_accum / (double)count;
            double loss = 1.0 - mean;
            if (loss < 0.0) loss = 0.0;
            if (loss > 1.0) loss = 1.0;
            out[0] = (float)loss;
            g_accum = 0.0;
            g_count = 0u;
        }
    }
}

extern "C" void kernel_launch(void* const* d_in, const int* in_sizes, int n_in,
                              void* d_out, int out_size) {
    const float* input  = (const float*)d_in[0];
    const float* target = (const float*)d_in[1];
    int sz0 = in_sizes[0], sz1 = in_sizes[1];
    if (sz0 > sz1) {
        const float* t = input; input = target; target = t;
        int ts = sz0; sz0 = sz1; sz1 = ts;
    }
    int n_img = sz0 / (HI * HI);   // 96

    dim3 grid(NT, NT, n_img);
    unsigned int nblocks = NT * NT * (unsigned int)n_img;
    long long count = (long long)n_img * HOUT * HOUT;

    ssim_tile_kernel<<<grid, 256>>>(input, target, (float*)d_out, count, nblocks);
}

// round 10
// speedup vs baseline: 1.0124x; 1.0124x over previous
#include <cuda_runtime.h>
#include <math.h>

// ---------------- problem constants ----------------
#define KS    11
#define HI    384
#define HO    512
#define HOUT  (HO - KS + 1)     // 502
#define TW    32                // tile width (outputs)
#define TH    64                // tile height (outputs)
#define PW    (TW + KS - 1)     // 42
#define PH    (TH + KS - 1)     // 74
#define SW    43                // s12 row stride (ull), odd -> conflict-free row walks
#define HS    33                // hbuf row stride (elements)
#define NTX   ((HOUT + TW - 1) / TW)   // 16
#define NTY   ((HOUT + TH - 1) / TH)   // 8
#define HTASKS (PH * 4)         // 296 tasks, 8 output cols each

typedef unsigned long long ull;

// Gaussian weights (sigma=1.5, ks=11), double-normalized, rounded to f32.
#define GW0  0.0010283801f
#define GW1  0.0075987582f
#define GW2  0.0360007722f
#define GW3  0.1093606884f
#define GW4  0.2130055383f
#define GW5  0.2660117256f

__device__ double        g_accum = 0.0;
__device__ unsigned int  g_count = 0;

// ---------------- f32x2 packed helpers ----------------
__device__ __forceinline__ ull splat2(float g) {
    ull r; asm("mov.b64 %0, {%1, %1};" : "=l"(r) : "f"(g)); return r;
}
__device__ __forceinline__ void up2(ull v, float& lo, float& hi) {
    asm("mov.b64 {%0, %1}, %2;" : "=f"(lo), "=f"(hi) : "l"(v));
}
__device__ __forceinline__ ull pk2(float lo, float hi) {
    ull r; asm("mov.b64 %0, {%1, %2};" : "=l"(r) : "f"(lo), "f"(hi)); return r;
}
__device__ __forceinline__ ull pfma(ull a, ull b, ull c) {
    ull d; asm("fma.rn.f32x2 %0, %1, %2, %3;" : "=l"(d) : "l"(a), "l"(b), "l"(c)); return d;
}
__device__ __forceinline__ ull pmul(ull a, ull b) {
    ull d; asm("mul.rn.f32x2 %0, %1, %2;" : "=l"(d) : "l"(a), "l"(b)); return d;
}

#define GWC(k) ((k) < 6 ? (k) : 10 - (k))

// ---- dynamic smem layout (bytes) ----
#define OFF_S12   0                                  // ull  [PH][SW] = 25456
#define OFF_HMU   (OFF_S12 + PH * SW * 8)            // ull  [PH][HS] = 19536
#define OFF_HSQ   (OFF_HMU + PH * HS * 8)            // ull  [PH][HS] = 19536
#define OFF_HX12  (OFF_HSQ + PH * HS * 8)            // f32  [PH][HS] =  9768
#define OFF_TBL   (OFF_HX12 + PH * HS * 4)
#define OFF_RED   (OFF_TBL + (PH * 4 + PW * 4) * 4)  // tables = 1856
#define SMEM_BYTES (OFF_RED + 64)                    // 76216 B; 3 CTAs/SM

// ---------------- single fused kernel ----------------
__global__ void __launch_bounds__(256, 3)
ssim_tile_kernel(const float* __restrict__ input,   // [96, 384, 384]
                 const float* __restrict__ target,  // [96, 512, 512]
                 float* __restrict__ out,
                 long long count, unsigned int nblocks)
{
    extern __shared__ char smem[];
    ull   (*s12)[SW]  = (ull (*)[SW])(smem + OFF_S12);
    ull   (*hmu)[HS]  = (ull (*)[HS])(smem + OFF_HMU);
    ull   (*hsq)[HS]  = (ull (*)[HS])(smem + OFF_HSQ);
    float (*hx12)[HS] = (float (*)[HS])(smem + OFF_HX12);
    int   *riy0 = (int*)  (smem + OFF_TBL);
    int   *riy1 = riy0 + PH;
    float *rwy  = (float*)(riy1 + PH);
    int   *rgy  = (int*)  (rwy + PH);
    int   *cix0 = rgy + PH;
    int   *cix1 = cix0 + PW;
    float *cwx  = (float*)(cix1 + PW);
    int   *cgx  = (int*)  (cwx + PW);
    float *redbuf = (float*)(smem + OFF_RED);

    const int img = blockIdx.z;
    const int ty0 = blockIdx.y * TH;
    const int tx0 = blockIdx.x * TW;
    const int tid = threadIdx.x;

    const float GW[6] = {GW0, GW1, GW2, GW3, GW4, GW5};
    ull CS[6];
    #pragma unroll
    for (int k = 0; k < 6; k++) CS[k] = splat2(GW[k]);

    const float* inp = input  + (size_t)img * (HI * HI);
    const float* tgt = target + (size_t)img * (HO * HO);

    // ---- build bilinear tables ----
    if (tid < PH) {
        int gy = min(ty0 + tid, HO - 1);
        int py = gy * (HI - 1);
        int iy0 = py / (HO - 1);
        riy0[tid] = iy0 * HI;
        riy1[tid] = min(iy0 + 1, HI - 1) * HI;
        rwy[tid]  = (float)(py - iy0 * (HO - 1)) * (1.0f / (float)(HO - 1));
        rgy[tid]  = gy * HO;
    }
    if (tid >= 128 && tid < 128 + PW) {
        int c = tid - 128;
        int gx = min(tx0 + c, HO - 1);
        int px = gx * (HI - 1);
        int ix0 = px / (HO - 1);
        cix0[c] = ix0;
        cix1[c] = min(ix0 + 1, HI - 1);
        cwx[c]  = (float)(px - ix0 * (HO - 1)) * (1.0f / (float)(HO - 1));
        cgx[c]  = gx;
    }
    __syncthreads();

    // ---- load: target direct, img1 bilinear via tables ----
    for (int e = tid; e < PH * PW; e += 256) {
        int r = e / PW;
        int c = e - r * PW;

        float t2 = tgt[rgy[r] + cgx[c]];

        int   y0 = riy0[r], y1 = riy1[r];
        float wy = rwy[r];
        int   x0 = cix0[c], x1 = cix1[c];
        float wx = cwx[c];

        float a  = inp[y0 + x0];
        float b  = inp[y0 + x1];
        float cc = inp[y1 + x0];
        float d  = inp[y1 + x1];
        float top = a  + (b - a)  * wx;
        float bot = cc + (d - cc) * wx;
        float v1  = top + (bot - top) * wy;

        s12[r][c] = pk2(v1, t2);
    }
    __syncthreads();

    // ---- horizontal pass: 8 output cols per task, sliding 18-tap window.
    //      Conflict-free map: consecutive lanes walk consecutive rows. ----
    for (int e = tid; e < HTASKS; e += 256) {
        int g  = e / PH;            // column group 0..3
        int r  = e - g * PH;        // row 0..73
        int c0 = g << 3;

        ull aM[8], aS[8];
        float aX[8];
        #pragma unroll
        for (int o = 0; o < 8; o++) { aM[o] = 0; aS[o] = 0; aX[o] = 0.f; }

        #pragma unroll
        for (int j = 0; j < 18; j++) {
            ull pk = s12[r][c0 + j];
            float p1, p2;
            up2(pk, p1, p2);
            ull sq = pmul(pk, pk);
            float p12 = p1 * p2;
            #pragma unroll
            for (int o = 0; o < 8; o++) {
                int k = j - o;
                if (k >= 0 && k < KS) {
                    aM[o] = pfma(pk, CS[GWC(k)], aM[o]);
                    aS[o] = pfma(sq, CS[GWC(k)], aS[o]);
                    aX[o] = fmaf(GW[GWC(k)], p12, aX[o]);
                }
            }
        }
        #pragma unroll
        for (int o = 0; o < 8; o++) {
            hmu[r][c0 + o]  = aM[o];
            hsq[r][c0 + o]  = aS[o];
            hx12[r][c0 + o] = aX[o];
        }
    }
    __syncthreads();

    // ---- vertical pass: 8 warps x 8 rows/thread, 18-tap window,
    //      software-pipelined smem loads ----
    const int lx = tid & 31;
    const int o0 = (tid >> 5) << 3;     // warp w -> rows 8w..8w+7

    ull aM[8], aS[8];
    float aX[8];
    #pragma unroll
    for (int o = 0; o < 8; o++) { aM[o] = 0; aS[o] = 0; aX[o] = 0.f; }

    ull vM   = hmu[o0][lx];
    ull vS   = hsq[o0][lx];
    float vX = hx12[o0][lx];

    #pragma unroll
    for (int rel = 0; rel < 18; rel++) {
        ull nM = 0, nS = 0; float nX = 0.f;
        if (rel < 17) {                 // prefetch next row
            int rr = o0 + rel + 1;
            nM = hmu[rr][lx];
            nS = hsq[rr][lx];
            nX = hx12[rr][lx];
        }
        #pragma unroll
        for (int o = 0; o < 8; o++) {
            int k = rel - o;
            if (k >= 0 && k < KS) {
                aM[o] = pfma(vM, CS[GWC(k)], aM[o]);
                aS[o] = pfma(vS, CS[GWC(k)], aS[o]);
                aX[o] = fmaf(GW[GWC(k)], vX, aX[o]);
            }
        }
        vM = nM; vS = nS; vX = nX;
    }

    // ---- SSIM map + local sum ----
    const float C1 = 1e-4f;
    const float C2 = 9e-4f;
    float lsum = 0.f;
    const int gx = tx0 + lx;

    #pragma unroll
    for (int o = 0; o < 8; o++) {
        int gy = ty0 + o0 + o;
        if (gy < HOUT && gx < HOUT) {
            float mu1, mu2, x11, x22;
            up2(aM[o], mu1, mu2);
            up2(aS[o], x11, x22);
            float mu1sq = mu1 * mu1;
            float mu2sq = mu2 * mu2;
            float mu12  = mu1 * mu2;
            float sig1  = x11 - mu1sq;
            float sig2  = x22 - mu2sq;
            float sig12 = aX[o] - mu12;
            float v1 = 2.0f * sig12 + C2;
            float v2 = sig1 + sig2 + C2;
            float num = (2.0f * mu12 + C1) * v1;
            float den = (mu1sq + mu2sq + C1) * v2;
            lsum += __fdividef(num, den);
        }
    }

    // ---- block reduction (8 warps) ----
    #pragma unroll
    for (int off = 16; off > 0; off >>= 1)
        lsum += __shfl_down_sync(0xFFFFFFFFu, lsum, off);
    int lane = tid & 31;
    int wid  = tid >> 5;
    if (lane == 0) redbuf[wid] = lsum;
    __syncthreads();
    if (tid == 0) {
        float v = 0.f;
        #pragma unroll
        for (int w = 0; w < 8; w++) v += redbuf[w];
        atomicAdd(&g_accum, (double)v);
        __threadfence();
        unsigned int old = atomicAdd(&g_count, 1u);
        if (old == nblocks - 1u) {
            double mean = g_accum / (double)count;
            double loss = 1.0 - mean;
            if (loss < 0.0) loss = 0.0;
            if (loss > 1.0) loss = 1.0;
            out[0] = (float)loss;
            g_accum = 0.0;
            g_count = 0u;
        }
    }
}

extern "C" void kernel_launch(void* const* d_in, const int* in_sizes, int n_in,
                              void* d_out, int out_size) {
    const float* input  = (const float*)d_in[0];
    const float* target = (const float*)d_in[1];
    int sz0 = in_sizes[0], sz1 = in_sizes[1];
    if (sz0 > sz1) {
        const float* t = input; input = target; target = t;
        int ts = sz0; sz0 = sz1; sz1 = ts;
    }
    int n_img = sz0 / (HI * HI);   // 96

    static bool attr_set = false;
    if (!attr_set) {
        cudaFuncSetAttribute(ssim_tile_kernel,
                             cudaFuncAttributeMaxDynamicSharedMemorySize, SMEM_BYTES);
        attr_set = true;
    }

    dim3 grid(NTX, NTY, n_img);
    unsigned int nblocks = NTX * NTY * (unsigned int)n_img;
    long long count = (long long)n_img * HOUT * HOUT;

    ssim_tile_kernel<<<grid, 256, SMEM_BYTES>>>(input, target, (float*)d_out,
                                                count, nblocks);
}

// round 11
// speedup vs baseline: 1.1878x; 1.1732x over previous
#include <cuda_runtime.h>
#include <math.h>

// ---------------- problem constants ----------------
#define KS    11
#define HI    384
#define HO    512
#define HOUT  (HO - KS + 1)     // 502
#define TW    32                // tile width (outputs)
#define TH    64                // tile height (outputs)
#define PW    (TW + KS - 1)     // 42
#define PH    (TH + KS - 1)     // 74
#define SW    43                // s12 row stride (ull), odd -> conflict-free row walks
#define HR    42                // hbuf ring rows
#define HS    33                // hbuf row stride (elements)
#define NTX   ((HOUT + TW - 1) / TW)   // 16
#define NTY   ((HOUT + TH - 1) / TH)   // 8

typedef unsigned long long ull;

// Gaussian weights (sigma=1.5, ks=11), double-normalized, rounded to f32.
#define GW0  0.0010283801f
#define GW1  0.0075987582f
#define GW2  0.0360007722f
#define GW3  0.1093606884f
#define GW4  0.2130055383f
#define GW5  0.2660117256f

__device__ double        g_accum = 0.0;
__device__ unsigned int  g_count = 0;

// ---------------- f32x2 packed helpers ----------------
__device__ __forceinline__ ull splat2(float g) {
    ull r; asm("mov.b64 %0, {%1, %1};" : "=l"(r) : "f"(g)); return r;
}
__device__ __forceinline__ void up2(ull v, float& lo, float& hi) {
    asm("mov.b64 {%0, %1}, %2;" : "=f"(lo), "=f"(hi) : "l"(v));
}
__device__ __forceinline__ ull pk2(float lo, float hi) {
    ull r; asm("mov.b64 %0, {%1, %2};" : "=l"(r) : "f"(lo), "f"(hi)); return r;
}
__device__ __forceinline__ ull pfma(ull a, ull b, ull c) {
    ull d; asm("fma.rn.f32x2 %0, %1, %2, %3;" : "=l"(d) : "l"(a), "l"(b), "l"(c)); return d;
}
__device__ __forceinline__ ull pmul(ull a, ull b) {
    ull d; asm("mul.rn.f32x2 %0, %1, %2;" : "=l"(d) : "l"(a), "l"(b)); return d;
}

#define GWC(k) ((k) < 6 ? (k) : 10 - (k))

// ---- dynamic smem layout (bytes) ----
#define OFF_S12   0                                  // ull  [PH][SW] = 25456
#define OFF_HMU   (OFF_S12 + PH * SW * 8)            // ull  [HR][HS] = 11088
#define OFF_HSQ   (OFF_HMU + HR * HS * 8)            // ull  [HR][HS] = 11088
#define OFF_HX12  (OFF_HSQ + HR * HS * 8)            // f32  [HR][HS] =  5544
#define OFF_TBL   (OFF_HX12 + HR * HS * 4)
#define OFF_RED   (OFF_TBL + (PH * 4 + PW * 4) * 4)  // tables = 1856
#define SMEM_BYTES (OFF_RED + 64)                    // 55096 B -> 4 CTAs/SM

// ---------------- single fused kernel ----------------
__global__ void __launch_bounds__(256, 4)
ssim_tile_kernel(const float* __restrict__ input,   // [96, 384, 384]
                 const float* __restrict__ target,  // [96, 512, 512]
                 float* __restrict__ out,
                 long long count, unsigned int nblocks)
{
    extern __shared__ char smem[];
    ull   (*s12)[SW]  = (ull (*)[SW])(smem + OFF_S12);
    ull   (*hmu)[HS]  = (ull (*)[HS])(smem + OFF_HMU);
    ull   (*hsq)[HS]  = (ull (*)[HS])(smem + OFF_HSQ);
    float (*hx12)[HS] = (float (*)[HS])(smem + OFF_HX12);
    int   *riy0 = (int*)  (smem + OFF_TBL);
    int   *riy1 = riy0 + PH;
    float *rwy  = (float*)(riy1 + PH);
    int   *rgy  = (int*)  (rwy + PH);
    int   *cix0 = rgy + PH;
    int   *cix1 = cix0 + PW;
    float *cwx  = (float*)(cix1 + PW);
    int   *cgx  = (int*)  (cwx + PW);
    float *redbuf = (float*)(smem + OFF_RED);

    const int img = blockIdx.z;
    const int ty0 = blockIdx.y * TH;
    const int tx0 = blockIdx.x * TW;
    const int tid = threadIdx.x;

    const float GW[6] = {GW0, GW1, GW2, GW3, GW4, GW5};
    ull CS[6];
    #pragma unroll
    for (int k = 0; k < 6; k++) CS[k] = splat2(GW[k]);

    const float* inp = input  + (size_t)img * (HI * HI);
    const float* tgt = target + (size_t)img * (HO * HO);

    // ---- build bilinear tables ----
    if (tid < PH) {
        int gy = min(ty0 + tid, HO - 1);
        int py = gy * (HI - 1);
        int iy0 = py / (HO - 1);
        riy0[tid] = iy0 * HI;
        riy1[tid] = min(iy0 + 1, HI - 1) * HI;
        rwy[tid]  = (float)(py - iy0 * (HO - 1)) * (1.0f / (float)(HO - 1));
        rgy[tid]  = gy * HO;
    }
    if (tid >= 128 && tid < 128 + PW) {
        int c = tid - 128;
        int gx = min(tx0 + c, HO - 1);
        int px = gx * (HI - 1);
        int ix0 = px / (HO - 1);
        cix0[c] = ix0;
        cix1[c] = min(ix0 + 1, HI - 1);
        cwx[c]  = (float)(px - ix0 * (HO - 1)) * (1.0f / (float)(HO - 1));
        cgx[c]  = gx;
    }
    __syncthreads();

    // ---- load full 74x42 patch: target direct, img1 bilinear via tables ----
    for (int e = tid; e < PH * PW; e += 256) {
        int r = e / PW;
        int c = e - r * PW;

        float t2 = tgt[rgy[r] + cgx[c]];

        int   y0 = riy0[r], y1 = riy1[r];
        float wy = rwy[r];
        int   x0 = cix0[c], x1 = cix1[c];
        float wx = cwx[c];

        float a  = inp[y0 + x0];
        float b  = inp[y0 + x1];
        float cc = inp[y1 + x0];
        float d  = inp[y1 + x1];
        float top = a  + (b - a)  * wx;
        float bot = cc + (d - cc) * wx;
        float v1  = top + (bot - top) * wy;

        s12[r][c] = pk2(v1, t2);
    }
    __syncthreads();

    const int lx = tid & 31;
    const int w  = tid >> 5;
    const int gx = tx0 + lx;
    const float C1 = 1e-4f;
    const float C2 = 9e-4f;
    float lsum = 0.f;

    // ======== two halves: hbuf is a 42-row ring (slot = row mod 42) ========
    #pragma unroll 1
    for (int half = 0; half < 2; half++) {
        // ---- horizontal pass for this half's new rows ----
        // half 0: rows 0..41 (slots 0..41); half 1: rows 42..73 (slots 0..31)
        const int base   = half ? HR : 0;
        const int nrows  = half ? (PH - HR) : HR;    // 32 : 42
        const int ntasks = nrows * 4;                // 8-output col groups

        for (int t = tid; t < ntasks; t += 256) {
            int g      = t / nrows;        // col group 0..3
            int rlocal = t - g * nrows;    // ring slot
            int r      = base + rlocal;    // s12 row
            int c0     = g << 3;

            ull aM[8], aS[8];
            float aX[8];
            #pragma unroll
            for (int o = 0; o < 8; o++) { aM[o] = 0; aS[o] = 0; aX[o] = 0.f; }

            #pragma unroll
            for (int j = 0; j < 18; j++) {
                ull pk = s12[r][c0 + j];
                float p1, p2;
                up2(pk, p1, p2);
                ull sq = pmul(pk, pk);
                float p12 = p1 * p2;
                #pragma unroll
                for (int o = 0; o < 8; o++) {
                    int k = j - o;
                    if (k >= 0 && k < KS) {
                        aM[o] = pfma(pk, CS[GWC(k)], aM[o]);
                        aS[o] = pfma(sq, CS[GWC(k)], aS[o]);
                        aX[o] = fmaf(GW[GWC(k)], p12, aX[o]);
                    }
                }
            }
            #pragma unroll
            for (int o = 0; o < 8; o++) {
                hmu[rlocal][c0 + o]  = aM[o];
                hsq[rlocal][c0 + o]  = aS[o];
                hx12[rlocal][c0 + o] = aX[o];
            }
        }
        __syncthreads();

        // ---- vertical pass: 8 warps x 4 rows/thread, 14-tap window ----
        const int v0 = half * 32 + (w << 2);   // first output row (local)

        ull aM[4], aS[4];
        float aX[4];
        #pragma unroll
        for (int o = 0; o < 4; o++) { aM[o] = 0; aS[o] = 0; aX[o] = 0.f; }

        #pragma unroll
        for (int rel = 0; rel < 14; rel++) {
            int rr   = v0 + rel;                    // h row 0..73
            int slot = (rr >= HR) ? (rr - HR) : rr; // ring slot
            ull vM   = hmu[slot][lx];
            ull vS   = hsq[slot][lx];
            float vX = hx12[slot][lx];
            #pragma unroll
            for (int o = 0; o < 4; o++) {
                int k = rel - o;
                if (k >= 0 && k < KS) {
                    aM[o] = pfma(vM, CS[GWC(k)], aM[o]);
                    aS[o] = pfma(vS, CS[GWC(k)], aS[o]);
                    aX[o] = fmaf(GW[GWC(k)], vX, aX[o]);
                }
            }
        }

        // ---- SSIM map + local sum for this half ----
        #pragma unroll
        for (int o = 0; o < 4; o++) {
            int gy = ty0 + v0 + o;
            if (gy < HOUT && gx < HOUT) {
                float mu1, mu2, x11, x22;
                up2(aM[o], mu1, mu2);
                up2(aS[o], x11, x22);
                float mu1sq = mu1 * mu1;
                float mu2sq = mu2 * mu2;
                float mu12  = mu1 * mu2;
                float sig1  = x11 - mu1sq;
                float sig2  = x22 - mu2sq;
                float sig12 = aX[o] - mu12;
                float v1 = 2.0f * sig12 + C2;
                float v2 = sig1 + sig2 + C2;
                float num = (2.0f * mu12 + C1) * v1;
                float den = (mu1sq + mu2sq + C1) * v2;
                lsum += __fdividef(num, den);
            }
        }
        __syncthreads();   // V reads done before next half's H overwrites ring
    }

    // ---- block reduction (8 warps) ----
    #pragma unroll
    for (int off = 16; off > 0; off >>= 1)
        lsum += __shfl_down_sync(0xFFFFFFFFu, lsum, off);
    if (lx == 0) redbuf[w] = lsum;
    __syncthreads();
    if (tid == 0) {
        float v = 0.f;
        #pragma unroll
        for (int ww = 0; ww < 8; ww++) v += redbuf[ww];
        atomicAdd(&g_accum, (double)v);
        __threadfence();
        unsigned int old = atomicAdd(&g_count, 1u);
        if (old == nblocks - 1u) {
            double mean = g_accum / (double)count;
            double loss = 1.0 - mean;
            if (loss < 0.0) loss = 0.0;
            if (loss > 1.0) loss = 1.0;
            out[0] = (float)loss;
            g_accum = 0.0;
            g_count = 0u;
        }
    }
}

extern "C" void kernel_launch(void* const* d_in, const int* in_sizes, int n_in,
                              void* d_out, int out_size) {
    const float* input  = (const float*)d_in[0];
    const float* target = (const float*)d_in[1];
    int sz0 = in_sizes[0], sz1 = in_sizes[1];
    if (sz0 > sz1) {
        const float* t = input; input = target; target = t;
        int ts = sz0; sz0 = sz1; sz1 = ts;
    }
    int n_img = sz0 / (HI * HI);   // 96

    static bool attr_set = false;
    if (!attr_set) {
        cudaFuncSetAttribute(ssim_tile_kernel,
                             cudaFuncAttributeMaxDynamicSharedMemorySize, SMEM_BYTES);
        attr_set = true;
    }

    dim3 grid(NTX, NTY, n_img);
    unsigned int nblocks = NTX * NTY * (unsigned int)n_img;
    long long count = (long long)n_img * HOUT * HOUT;

    ssim_tile_kernel<<<grid, 256, SMEM_BYTES>>>(input, target, (float*)d_out,
                                                count, nblocks);
}

// round 12
// speedup vs baseline: 1.2559x; 1.0573x over previous
#include <cuda_runtime.h>
#include <math.h>

// ---------------- problem constants ----------------
#define KS    11
#define HI    384
#define HO    512
#define HOUT  (HO - KS + 1)     // 502
#define TW    32                // tile width (outputs)
#define TH    64                // tile height (outputs)
#define PW    (TW + KS - 1)     // 42
#define PH    (TH + KS - 1)     // 74
#define SW    43                // s12 row stride (ull), odd -> conflict-free row walks
#define HR    42                // hbuf ring rows
#define HS    33                // hbuf row stride (elements)
#define NTX   ((HOUT + TW - 1) / TW)   // 16
#define NTY   ((HOUT + TH - 1) / TH)   // 8

typedef unsigned long long ull;

// Gaussian weights (sigma=1.5, ks=11), double-normalized, rounded to f32.
#define GW0  0.0010283801f
#define GW1  0.0075987582f
#define GW2  0.0360007722f
#define GW3  0.1093606884f
#define GW4  0.2130055383f
#define GW5  0.2660117256f

__device__ double        g_accum = 0.0;
__device__ unsigned int  g_count = 0;

// ---------------- f32x2 packed helpers ----------------
__device__ __forceinline__ ull splat2(float g) {
    ull r; asm("mov.b64 %0, {%1, %1};" : "=l"(r) : "f"(g)); return r;
}
__device__ __forceinline__ void up2(ull v, float& lo, float& hi) {
    asm("mov.b64 {%0, %1}, %2;" : "=f"(lo), "=f"(hi) : "l"(v));
}
__device__ __forceinline__ ull pk2(float lo, float hi) {
    ull r; asm("mov.b64 %0, {%1, %2};" : "=l"(r) : "f"(lo), "f"(hi)); return r;
}
__device__ __forceinline__ ull pfma(ull a, ull b, ull c) {
    ull d; asm("fma.rn.f32x2 %0, %1, %2, %3;" : "=l"(d) : "l"(a), "l"(b), "l"(c)); return d;
}
__device__ __forceinline__ ull pmul(ull a, ull b) {
    ull d; asm("mul.rn.f32x2 %0, %1, %2;" : "=l"(d) : "l"(a), "l"(b)); return d;
}

#define GWC(k) ((k) < 6 ? (k) : 10 - (k))

// ---- dynamic smem layout (bytes) ----
#define OFF_S12   0                                  // ull [PH][SW] = 25456
#define OFF_HMU   (OFF_S12 + PH * SW * 8)            // ull [HR][HS] = 11088  (mu1h, mu2h)
#define OFF_HSX   (OFF_HMU + HR * HS * 8)            // ull [HR][HS] = 11088  (x11h+x22h, x12h)
#define OFF_TBL   (OFF_HSX + HR * HS * 8)
#define OFF_RED   (OFF_TBL + (PH * 4 + PW * 4) * 4)  // tables = 1856
#define SMEM_BYTES (OFF_RED + 64)                    // 49552 B -> 4 CTAs/SM

// ---------------- single fused kernel ----------------
__global__ void __launch_bounds__(256, 4)
ssim_tile_kernel(const float* __restrict__ input,   // [96, 384, 384]
                 const float* __restrict__ target,  // [96, 512, 512]
                 float* __restrict__ out,
                 long long count, unsigned int nblocks)
{
    extern __shared__ char smem[];
    ull   (*s12)[SW] = (ull (*)[SW])(smem + OFF_S12);
    ull   (*hmu)[HS] = (ull (*)[HS])(smem + OFF_HMU);
    ull   (*hsx)[HS] = (ull (*)[HS])(smem + OFF_HSX);
    int   *riy0 = (int*)  (smem + OFF_TBL);
    int   *riy1 = riy0 + PH;
    float *rwy  = (float*)(riy1 + PH);
    int   *rgy  = (int*)  (rwy + PH);
    int   *cix0 = rgy + PH;
    int   *cix1 = cix0 + PW;
    float *cwx  = (float*)(cix1 + PW);
    int   *cgx  = (int*)  (cwx + PW);
    float *redbuf = (float*)(smem + OFF_RED);

    const int img = blockIdx.z;
    const int ty0 = blockIdx.y * TH;
    const int tx0 = blockIdx.x * TW;
    const int tid = threadIdx.x;

    const float GW[6] = {GW0, GW1, GW2, GW3, GW4, GW5};
    ull CS[6];
    #pragma unroll
    for (int k = 0; k < 6; k++) CS[k] = splat2(GW[k]);

    const float* inp = input  + (size_t)img * (HI * HI);
    const float* tgt = target + (size_t)img * (HO * HO);

    // ---- build bilinear tables ----
    if (tid < PH) {
        int gy = min(ty0 + tid, HO - 1);
        int py = gy * (HI - 1);
        int iy0 = py / (HO - 1);
        riy0[tid] = iy0 * HI;
        riy1[tid] = min(iy0 + 1, HI - 1) * HI;
        rwy[tid]  = (float)(py - iy0 * (HO - 1)) * (1.0f / (float)(HO - 1));
        rgy[tid]  = gy * HO;
    }
    if (tid >= 128 && tid < 128 + PW) {
        int c = tid - 128;
        int gx = min(tx0 + c, HO - 1);
        int px = gx * (HI - 1);
        int ix0 = px / (HO - 1);
        cix0[c] = ix0;
        cix1[c] = min(ix0 + 1, HI - 1);
        cwx[c]  = (float)(px - ix0 * (HO - 1)) * (1.0f / (float)(HO - 1));
        cgx[c]  = gx;
    }
    __syncthreads();

    // ---- load full 74x42 patch: target direct, img1 bilinear via tables ----
    for (int e = tid; e < PH * PW; e += 256) {
        int r = e / PW;
        int c = e - r * PW;

        float t2 = tgt[rgy[r] + cgx[c]];

        int   y0 = riy0[r], y1 = riy1[r];
        float wy = rwy[r];
        int   x0 = cix0[c], x1 = cix1[c];
        float wx = cwx[c];

        float a  = inp[y0 + x0];
        float b  = inp[y0 + x1];
        float cc = inp[y1 + x0];
        float d  = inp[y1 + x1];
        float top = a  + (b - a)  * wx;
        float bot = cc + (d - cc) * wx;
        float v1  = top + (bot - top) * wy;

        s12[r][c] = pk2(v1, t2);
    }
    __syncthreads();

    const int lx = tid & 31;
    const int w  = tid >> 5;
    const int gx = tx0 + lx;
    const float C1 = 1e-4f;
    const float C2 = 9e-4f;
    float lsum = 0.f;

    // ======== two halves: hbuf is a 42-row ring (slot = row mod 42) ========
    #pragma unroll 1
    for (int half = 0; half < 2; half++) {
        // ---- horizontal pass for this half's new rows ----
        // half 0: rows 0..41 (slots 0..41); half 1: rows 42..73 (slots 0..31)
        const int base   = half ? HR : 0;
        const int nrows  = half ? (PH - HR) : HR;    // 32 : 42
        const int ntasks = nrows * 4;                // 8-output col groups

        for (int t = tid; t < ntasks; t += 256) {
            int g      = t / nrows;        // col group 0..3
            int rlocal = t - g * nrows;    // ring slot
            int r      = base + rlocal;    // s12 row
            int c0     = g << 3;

            ull aM[8], aSX[8];
            #pragma unroll
            for (int o = 0; o < 8; o++) { aM[o] = 0; aSX[o] = 0; }

            #pragma unroll
            for (int j = 0; j < 18; j++) {
                ull pk = s12[r][c0 + j];
                float p1, p2;
                up2(pk, p1, p2);
                ull sq = pmul(pk, pk);
                float s1, s2;
                up2(sq, s1, s2);
                ull sx = pk2(s1 + s2, p1 * p2);   // (p1^2+p2^2, p1*p2)
                #pragma unroll
                for (int o = 0; o < 8; o++) {
                    int k = j - o;
                    if (k >= 0 && k < KS) {
                        aM[o]  = pfma(pk, CS[GWC(k)], aM[o]);
                        aSX[o] = pfma(sx, CS[GWC(k)], aSX[o]);
                    }
                }
            }
            #pragma unroll
            for (int o = 0; o < 8; o++) {
                hmu[rlocal][c0 + o] = aM[o];
                hsx[rlocal][c0 + o] = aSX[o];
            }
        }
        __syncthreads();

        // ---- vertical pass: 8 warps x 4 rows/thread, 14-tap window ----
        const int v0 = half * 32 + (w << 2);   // first output row (local)

        ull aM[4], aSX[4];
        #pragma unroll
        for (int o = 0; o < 4; o++) { aM[o] = 0; aSX[o] = 0; }

        #pragma unroll
        for (int rel = 0; rel < 14; rel++) {
            int rr   = v0 + rel;                    // h row 0..73
            int slot = (rr >= HR) ? (rr - HR) : rr; // ring slot
            ull vM  = hmu[slot][lx];
            ull vSX = hsx[slot][lx];
            #pragma unroll
            for (int o = 0; o < 4; o++) {
                int k = rel - o;
                if (k >= 0 && k < KS) {
                    aM[o]  = pfma(vM,  CS[GWC(k)], aM[o]);
                    aSX[o] = pfma(vSX, CS[GWC(k)], aSX[o]);
                }
            }
        }

        // ---- SSIM map + local sum for this half ----
        #pragma unroll
        for (int o = 0; o < 4; o++) {
            int gy = ty0 + v0 + o;
            if (gy < HOUT && gx < HOUT) {
                float mu1, mu2, xsum, x12;
                up2(aM[o], mu1, mu2);
                up2(aSX[o], xsum, x12);
                float mu1sq = mu1 * mu1;
                float mu2sq = mu2 * mu2;
                float mu12  = mu1 * mu2;
                float sigsum = xsum - mu1sq - mu2sq;  // sigma1_sq + sigma2_sq
                float sig12  = x12  - mu12;
                float v1 = 2.0f * sig12 + C2;
                float v2 = sigsum + C2;
                float num = (2.0f * mu12 + C1) * v1;
                float den = (mu1sq + mu2sq + C1) * v2;
                lsum += __fdividef(num, den);
            }
        }
        __syncthreads();   // V reads done before next half's H overwrites ring
    }

    // ---- block reduction (8 warps) ----
    #pragma unroll
    for (int off = 16; off > 0; off >>= 1)
        lsum += __shfl_down_sync(0xFFFFFFFFu, lsum, off);
    if (lx == 0) redbuf[w] = lsum;
    __syncthreads();
    if (tid == 0) {
        float v = 0.f;
        #pragma unroll
        for (int ww = 0; ww < 8; ww++) v += redbuf[ww];
        atomicAdd(&g_accum, (double)v);
        __threadfence();
        unsigned int old = atomicAdd(&g_count, 1u);
        if (old == nblocks - 1u) {
            double mean = g_accum / (double)count;
            double loss = 1.0 - mean;
            if (loss < 0.0) loss = 0.0;
            if (loss > 1.0) loss = 1.0;
            out[0] = (float)loss;
            g_accum = 0.0;
            g_count = 0u;
        }
    }
}

extern "C" void kernel_launch(void* const* d_in, const int* in_sizes, int n_in,
                              void* d_out, int out_size) {
    const float* input  = (const float*)d_in[0];
    const float* target = (const float*)d_in[1];
    int sz0 = in_sizes[0], sz1 = in_sizes[1];
    if (sz0 > sz1) {
        const float* t = input; input = target; target = t;
        int ts = sz0; sz0 = sz1; sz1 = ts;
    }
    int n_img = sz0 / (HI * HI);   // 96

    static bool attr_set = false;
    if (!attr_set) {
        cudaFuncSetAttribute(ssim_tile_kernel,
                             cudaFuncAttributeMaxDynamicSharedMemorySize, SMEM_BYTES);
        attr_set = true;
    }

    dim3 grid(NTX, NTY, n_img);
    unsigned int nblocks = NTX * NTY * (unsigned int)n_img;
    long long count = (long long)n_img * HOUT * HOUT;

    ssim_tile_kernel<<<grid, 256, SMEM_BYTES>>>(input, target, (float*)d_out,
                                                count, nblocks);
}

// round 13
// speedup vs baseline: 1.2840x; 1.0224x over previous
#include <cuda_runtime.h>
#include <math.h>

// ---------------- problem constants ----------------
#define KS    11
#define HI    384
#define HO    512
#define HOUT  (HO - KS + 1)     // 502
#define TW    32                // tile width (outputs)
#define TH    64                // tile height (outputs)
#define PW    (TW + KS - 1)     // 42
#define PH    (TH + KS - 1)     // 74
#define SR    42                // s12 ring rows
#define SW    43                // s12 row stride (ull), odd -> conflict-free row walks
#define HS    33                // hbuf row stride (elements)
#define NTX   ((HOUT + TW - 1) / TW)   // 16
#define NTY   ((HOUT + TH - 1) / TH)   // 8

typedef unsigned long long ull;

// Gaussian weights (sigma=1.5, ks=11), double-normalized, rounded to f32.
#define GW0  0.0010283801f
#define GW1  0.0075987582f
#define GW2  0.0360007722f
#define GW3  0.1093606884f
#define GW4  0.2130055383f
#define GW5  0.2660117256f

__device__ double        g_accum = 0.0;
__device__ unsigned int  g_count = 0;

// ---------------- f32x2 packed helpers ----------------
__device__ __forceinline__ ull splat2(float g) {
    ull r; asm("mov.b64 %0, {%1, %1};" : "=l"(r) : "f"(g)); return r;
}
__device__ __forceinline__ void up2(ull v, float& lo, float& hi) {
    asm("mov.b64 {%0, %1}, %2;" : "=f"(lo), "=f"(hi) : "l"(v));
}
__device__ __forceinline__ ull pk2(float lo, float hi) {
    ull r; asm("mov.b64 %0, {%1, %2};" : "=l"(r) : "f"(lo), "f"(hi)); return r;
}
__device__ __forceinline__ ull pfma(ull a, ull b, ull c) {
    ull d; asm("fma.rn.f32x2 %0, %1, %2, %3;" : "=l"(d) : "l"(a), "l"(b), "l"(c)); return d;
}
__device__ __forceinline__ ull pmul(ull a, ull b) {
    ull d; asm("mul.rn.f32x2 %0, %1, %2;" : "=l"(d) : "l"(a), "l"(b)); return d;
}

#define GWC(k) ((k) < 6 ? (k) : 10 - (k))

// ---- dynamic smem layout (bytes) ----
#define OFF_S12   0                                  // ull [SR][SW] = 14448 (ring)
#define OFF_HMU   (OFF_S12 + SR * SW * 8)            // ull [PH][HS] = 19536 (mu1h, mu2h)
#define OFF_HSX   (OFF_HMU + PH * HS * 8)            // ull [PH][HS] = 19536 (x11h+x22h, x12h)
#define OFF_TBL   (OFF_HSX + PH * HS * 8)
#define OFF_RED   (OFF_TBL + (PH * 4 + PW * 4) * 4)  // tables = 1856
#define SMEM_BYTES (OFF_RED + 64)                    // 55440 B -> 4 CTAs/SM

// ---------------- single fused kernel ----------------
__global__ void __launch_bounds__(256, 4)
ssim_tile_kernel(const float* __restrict__ input,   // [96, 384, 384]
                 const float* __restrict__ target,  // [96, 512, 512]
                 float* __restrict__ out,
                 long long count, unsigned int nblocks)
{
    extern __shared__ char smem[];
    ull   (*s12)[SW] = (ull (*)[SW])(smem + OFF_S12);
    ull   (*hmu)[HS] = (ull (*)[HS])(smem + OFF_HMU);
    ull   (*hsx)[HS] = (ull (*)[HS])(smem + OFF_HSX);
    int   *riy0 = (int*)  (smem + OFF_TBL);
    int   *riy1 = riy0 + PH;
    float *rwy  = (float*)(riy1 + PH);
    int   *rgy  = (int*)  (rwy + PH);
    int   *cix0 = rgy + PH;
    int   *cix1 = cix0 + PW;
    float *cwx  = (float*)(cix1 + PW);
    int   *cgx  = (int*)  (cwx + PW);
    float *redbuf = (float*)(smem + OFF_RED);

    const int img = blockIdx.z;
    const int ty0 = blockIdx.y * TH;
    const int tx0 = blockIdx.x * TW;
    const int tid = threadIdx.x;

    const float GW[6] = {GW0, GW1, GW2, GW3, GW4, GW5};
    ull CS[6];
    #pragma unroll
    for (int k = 0; k < 6; k++) CS[k] = splat2(GW[k]);

    const float* inp = input  + (size_t)img * (HI * HI);
    const float* tgt = target + (size_t)img * (HO * HO);

    // ---- build bilinear tables ----
    if (tid < PH) {
        int gy = min(ty0 + tid, HO - 1);
        int py = gy * (HI - 1);
        int iy0 = py / (HO - 1);
        riy0[tid] = iy0 * HI;
        riy1[tid] = min(iy0 + 1, HI - 1) * HI;
        rwy[tid]  = (float)(py - iy0 * (HO - 1)) * (1.0f / (float)(HO - 1));
        rgy[tid]  = gy * HO;
    }
    if (tid >= 128 && tid < 128 + PW) {
        int c = tid - 128;
        int gx = min(tx0 + c, HO - 1);
        int px = gx * (HI - 1);
        int ix0 = px / (HO - 1);
        cix0[c] = ix0;
        cix1[c] = min(ix0 + 1, HI - 1);
        cwx[c]  = (float)(px - ix0 * (HO - 1)) * (1.0f / (float)(HO - 1));
        cgx[c]  = gx;
    }
    __syncthreads();

    // ======== two chunks: s12 is a 42-row ring (slot = row mod 42) ========
    // chunk 0: patch rows 0..41 -> slots 0..41
    // chunk 1: patch rows 42..73 -> slots 0..31 (H of chunk 0 done by then)
    #pragma unroll 1
    for (int chunk = 0; chunk < 2; chunk++) {
        const int r0    = chunk ? SR : 0;
        const int nrows = chunk ? (PH - SR) : SR;    // 32 : 42

        // ---- load chunk: target direct, img1 bilinear via tables ----
        for (int e = tid; e < nrows * PW; e += 256) {
            int rl = e / PW;            // ring slot
            int c  = e - rl * PW;
            int r  = r0 + rl;           // patch row

            float t2 = tgt[rgy[r] + cgx[c]];

            int   y0 = riy0[r], y1 = riy1[r];
            float wy = rwy[r];
            int   x0 = cix0[c], x1 = cix1[c];
            float wx = cwx[c];

            float a  = inp[y0 + x0];
            float b  = inp[y0 + x1];
            float cc = inp[y1 + x0];
            float d  = inp[y1 + x1];
            float top = a  + (b - a)  * wx;
            float bot = cc + (d - cc) * wx;
            float v1  = top + (bot - top) * wy;

            s12[rl][c] = pk2(v1, t2);
        }
        __syncthreads();

        // ---- horizontal pass for this chunk's rows ----
        const int ntasks = nrows * 4;   // 8-output col groups

        for (int t = tid; t < ntasks; t += 256) {
            int g  = t / nrows;         // col group 0..3
            int rl = t - g * nrows;     // ring slot
            int r  = r0 + rl;           // patch row (hbuf row)
            int c0 = g << 3;

            ull aM[8], aSX[8];
            #pragma unroll
            for (int o = 0; o < 8; o++) { aM[o] = 0; aSX[o] = 0; }

            #pragma unroll
            for (int j = 0; j < 18; j++) {
                ull pk = s12[rl][c0 + j];
                float p1, p2;
                up2(pk, p1, p2);
                ull sq = pmul(pk, pk);
                float s1, s2;
                up2(sq, s1, s2);
                ull sx = pk2(s1 + s2, p1 * p2);   // (p1^2+p2^2, p1*p2)
                #pragma unroll
                for (int o = 0; o < 8; o++) {
                    int k = j - o;
                    if (k >= 0 && k < KS) {
                        aM[o]  = pfma(pk, CS[GWC(k)], aM[o]);
                        aSX[o] = pfma(sx, CS[GWC(k)], aSX[o]);
                    }
                }
            }
            #pragma unroll
            for (int o = 0; o < 8; o++) {
                hmu[r][c0 + o] = aM[o];
                hsx[r][c0 + o] = aSX[o];
            }
        }
        __syncthreads();
    }

    // ---- vertical pass: 8 warps x 8 rows/thread, 18-tap window, linear hbuf ----
    const int lx = tid & 31;
    const int w  = tid >> 5;
    const int v0 = w << 3;              // warp w -> output rows 8w..8w+7
    const int gx = tx0 + lx;
    const float C1 = 1e-4f;
    const float C2 = 9e-4f;
    float lsum = 0.f;

    ull aM[8], aSX[8];
    #pragma unroll
    for (int o = 0; o < 8; o++) { aM[o] = 0; aSX[o] = 0; }

    #pragma unroll
    for (int rel = 0; rel < 18; rel++) {
        int rr = v0 + rel;
        ull vM  = hmu[rr][lx];
        ull vSX = hsx[rr][lx];
        #pragma unroll
        for (int o = 0; o < 8; o++) {
            int k = rel - o;
            if (k >= 0 && k < KS) {
                aM[o]  = pfma(vM,  CS[GWC(k)], aM[o]);
                aSX[o] = pfma(vSX, CS[GWC(k)], aSX[o]);
            }
        }
    }

    // ---- SSIM map + local sum ----
    #pragma unroll
    for (int o = 0; o < 8; o++) {
        int gy = ty0 + v0 + o;
        if (gy < HOUT && gx < HOUT) {
            float mu1, mu2, xsum, x12;
            up2(aM[o], mu1, mu2);
            up2(aSX[o], xsum, x12);
            float mu1sq = mu1 * mu1;
            float mu2sq = mu2 * mu2;
            float mu12  = mu1 * mu2;
            float sigsum = xsum - mu1sq - mu2sq;  // sigma1_sq + sigma2_sq
            float sig12  = x12  - mu12;
            float v1 = 2.0f * sig12 + C2;
            float v2 = sigsum + C2;
            float num = (2.0f * mu12 + C1) * v1;
            float den = (mu1sq + mu2sq + C1) * v2;
            lsum += __fdividef(num, den);
        }
    }

    // ---- block reduction (8 warps) ----
    #pragma unroll
    for (int off = 16; off > 0; off >>= 1)
        lsum += __shfl_down_sync(0xFFFFFFFFu, lsum, off);
    if (lx == 0) redbuf[w] = lsum;
    __syncthreads();
    if (tid == 0) {
        float v = 0.f;
        #pragma unroll
        for (int ww = 0; ww < 8; ww++) v += redbuf[ww];
        atomicAdd(&g_accum, (double)v);
        __threadfence();
        unsigned int old = atomicAdd(&g_count, 1u);
        if (old == nblocks - 1u) {
            double mean = g_accum / (double)count;
            double loss = 1.0 - mean;
            if (loss < 0.0) loss = 0.0;
            if (loss > 1.0) loss = 1.0;
            out[0] = (float)loss;
            g_accum = 0.0;
            g_count = 0u;
        }
    }
}

extern "C" void kernel_launch(void* const* d_in, const int* in_sizes, int n_in,
                              void* d_out, int out_size) {
    const float* input  = (const float*)d_in[0];
    const float* target = (const float*)d_in[1];
    int sz0 = in_sizes[0], sz1 = in_sizes[1];
    if (sz0 > sz1) {
        const float* t = input; input = target; target = t;
        int ts = sz0; sz0 = sz1; sz1 = ts;
    }
    int n_img = sz0 / (HI * HI);   // 96

    static bool attr_set = false;
    if (!attr_set) {
        cudaFuncSetAttribute(ssim_tile_kernel,
                             cudaFuncAttributeMaxDynamicSharedMemorySize, SMEM_BYTES);
        attr_set = true;
    }

    dim3 grid(NTX, NTY, n_img);
    unsigned int nblocks = NTX * NTY * (unsigned int)n_img;
    long long count = (long long)n_img * HOUT * HOUT;

    ssim_tile_kernel<<<grid, 256, SMEM_BYTES>>>(input, target, (float*)d_out,
                                                count, nblocks);
}